// round 1
// baseline (speedup 1.0000x reference)
#include <cuda_runtime.h>
#include <math_constants.h>

// Problem dims (fixed by the reference)
#define BB 8
#define SS 2048
#define DD 512

// Scratch (allocation-free rule: __device__ globals)
__device__ float g_q[(size_t)BB * SS * DD];
__device__ float g_k[(size_t)BB * SS * DD];
__device__ float g_v[(size_t)BB * SS * DD];
__device__ float g_p[(size_t)BB * SS * SS];   // scores / probs, 128 MiB

// ---------------------------------------------------------------------------
// Classic register-blocked SGEMM.
//   C[M,N] = A[M,K] @ B(' if TRANS_B)   (+ bias[N] if HAS_BIAS)
// A row-major lda=K. B row-major: NN -> [K,N] ldb=N ; NT -> [N,K] ldb=K.
// Block tile 128x128, K-tile 16, 256 threads, 8x8 per-thread microtile.
// blockIdx.z = batch; per-batch element strides sA/sB/sC.
// All dims here are multiples of the tile sizes (128/16) -> no bounds checks.
// ---------------------------------------------------------------------------
template <bool TRANS_B, bool HAS_BIAS>
__global__ __launch_bounds__(256)
void sgemm(const float* __restrict__ A, const float* __restrict__ Bm,
           const float* __restrict__ bias, float* __restrict__ C,
           int M, int N, int K,
           long long sA, long long sB, long long sC)
{
    constexpr int BM = 128, BN = 128, BK = 16;
    A  += (long long)blockIdx.z * sA;
    Bm += (long long)blockIdx.z * sB;
    C  += (long long)blockIdx.z * sC;

    __shared__ float As[BK][BM + 1];
    __shared__ float Bs[BK][BN + 1];

    const int tid = threadIdx.x;
    const int tx = tid & 15;        // 0..15 -> col group
    const int ty = tid >> 4;        // 0..15 -> row group
    const int bm = blockIdx.y * BM;
    const int bn = blockIdx.x * BN;

    float acc[8][8];
    #pragma unroll
    for (int i = 0; i < 8; i++)
        #pragma unroll
        for (int j = 0; j < 8; j++) acc[i][j] = 0.f;

    for (int kk = 0; kk < K; kk += BK) {
        // ---- load A tile [BM][BK] -> As[k][m] (transposed stage) ----
        #pragma unroll
        for (int i = 0; i < 2; i++) {
            int idx = tid + i * 256;          // 512 float4 total
            int row = idx >> 2;               // 0..127
            int c4  = (idx & 3) * 4;          // 0,4,8,12
            float4 v = *(const float4*)(A + (long long)(bm + row) * K + kk + c4);
            As[c4 + 0][row] = v.x;
            As[c4 + 1][row] = v.y;
            As[c4 + 2][row] = v.z;
            As[c4 + 3][row] = v.w;
        }
        // ---- load B tile -> Bs[k][n] ----
        if (TRANS_B) {
            // B is [N,K]; tile rows n in [bn,bn+BN), cols kk..kk+BK
            #pragma unroll
            for (int i = 0; i < 2; i++) {
                int idx = tid + i * 256;
                int row = idx >> 2;           // n within tile
                int c4  = (idx & 3) * 4;      // k within tile
                float4 v = *(const float4*)(Bm + (long long)(bn + row) * K + kk + c4);
                Bs[c4 + 0][row] = v.x;
                Bs[c4 + 1][row] = v.y;
                Bs[c4 + 2][row] = v.z;
                Bs[c4 + 3][row] = v.w;
            }
        } else {
            // B is [K,N]; tile rows kk..kk+BK, cols bn..bn+BN
            #pragma unroll
            for (int i = 0; i < 2; i++) {
                int idx = tid + i * 256;
                int row = idx >> 5;           // 0..15 (k)
                int c4  = (idx & 31) * 4;     // 0..124 (n)
                float4 v = *(const float4*)(Bm + (long long)(kk + row) * N + bn + c4);
                Bs[row][c4 + 0] = v.x;
                Bs[row][c4 + 1] = v.y;
                Bs[row][c4 + 2] = v.z;
                Bs[row][c4 + 3] = v.w;
            }
        }
        __syncthreads();

        // ---- FMA microkernel ----
        #pragma unroll
        for (int k = 0; k < BK; k++) {
            float a[8], b[8];
            #pragma unroll
            for (int i = 0; i < 8; i++) a[i] = As[k][ty * 8 + i];
            #pragma unroll
            for (int j = 0; j < 8; j++) b[j] = Bs[k][tx * 8 + j];
            #pragma unroll
            for (int i = 0; i < 8; i++)
                #pragma unroll
                for (int j = 0; j < 8; j++)
                    acc[i][j] = fmaf(a[i], b[j], acc[i][j]);
        }
        __syncthreads();
    }

    // ---- epilogue (+bias) ----
    #pragma unroll
    for (int i = 0; i < 8; i++) {
        long long crow = (long long)(bm + ty * 8 + i) * N + bn + tx * 8;
        #pragma unroll
        for (int j = 0; j < 8; j += 4) {
            float4 o;
            if (HAS_BIAS) {
                o.x = acc[i][j + 0] + bias[bn + tx * 8 + j + 0];
                o.y = acc[i][j + 1] + bias[bn + tx * 8 + j + 1];
                o.z = acc[i][j + 2] + bias[bn + tx * 8 + j + 2];
                o.w = acc[i][j + 3] + bias[bn + tx * 8 + j + 3];
            } else {
                o.x = acc[i][j + 0];
                o.y = acc[i][j + 1];
                o.z = acc[i][j + 2];
                o.w = acc[i][j + 3];
            }
            *(float4*)(C + crow + j) = o;
        }
    }
}

// ---------------------------------------------------------------------------
// Row softmax, in-place. One block per row of 2048 floats; 256 threads x 8.
// ---------------------------------------------------------------------------
__global__ __launch_bounds__(256)
void softmax_rows(float* __restrict__ p)
{
    __shared__ float red[32];
    const long long row = blockIdx.x;
    float* r = p + row * (long long)SS;
    const int tid = threadIdx.x;
    const int lane = tid & 31, wid = tid >> 5;

    float v[8];
    float m = -CUDART_INF_F;
    #pragma unroll
    for (int i = 0; i < 8; i++) {
        v[i] = r[tid + i * 256];
        m = fmaxf(m, v[i]);
    }
    // block max
    #pragma unroll
    for (int o = 16; o > 0; o >>= 1) m = fmaxf(m, __shfl_xor_sync(0xffffffffu, m, o));
    if (lane == 0) red[wid] = m;
    __syncthreads();
    if (wid == 0) {
        float t = (lane < 8) ? red[lane] : -CUDART_INF_F;
        #pragma unroll
        for (int o = 16; o > 0; o >>= 1) t = fmaxf(t, __shfl_xor_sync(0xffffffffu, t, o));
        red[lane] = t;   // all lanes hold block max; lane0's write suffices
    }
    __syncthreads();
    m = red[0];

    float s = 0.f;
    #pragma unroll
    for (int i = 0; i < 8; i++) {
        v[i] = expf(v[i] - m);
        s += v[i];
    }
    #pragma unroll
    for (int o = 16; o > 0; o >>= 1) s += __shfl_xor_sync(0xffffffffu, s, o);
    __syncthreads();
    if (lane == 0) red[wid] = s;
    __syncthreads();
    if (wid == 0) {
        float t = (lane < 8) ? red[lane] : 0.f;
        #pragma unroll
        for (int o = 16; o > 0; o >>= 1) t += __shfl_xor_sync(0xffffffffu, t, o);
        red[lane] = t;
    }
    __syncthreads();
    const float inv = 1.0f / red[0];

    #pragma unroll
    for (int i = 0; i < 8; i++) r[tid + i * 256] = v[i] * inv;
}

// ---------------------------------------------------------------------------
extern "C" void kernel_launch(void* const* d_in, const int* in_sizes, int n_in,
                              void* d_out, int out_size)
{
    const float* x  = (const float*)d_in[0];
    const float* Wq = (const float*)d_in[1];
    const float* bq = (const float*)d_in[2];
    const float* Wk = (const float*)d_in[3];
    const float* bk = (const float*)d_in[4];
    const float* Wv = (const float*)d_in[5];
    const float* bv = (const float*)d_in[6];
    float* out = (float*)d_out;

    float *q, *k, *v, *p;
    cudaGetSymbolAddress((void**)&q, g_q);
    cudaGetSymbolAddress((void**)&k, g_k);
    cudaGetSymbolAddress((void**)&v, g_v);
    cudaGetSymbolAddress((void**)&p, g_p);

    const int M = BB * SS;       // 16384 rows for projections

    // 1-3) q/k/v = x @ W + b   (M=16384, N=512, K=512)
    {
        dim3 grid(DD / 128, M / 128, 1);
        sgemm<false, true><<<grid, 256>>>(x, Wq, bq, q, M, DD, DD, 0, 0, 0);
        sgemm<false, true><<<grid, 256>>>(x, Wk, bk, k, M, DD, DD, 0, 0, 0);
        sgemm<false, true><<<grid, 256>>>(x, Wv, bv, v, M, DD, DD, 0, 0, 0);
    }

    // 4) scores = q @ k^T per batch  (M=N=2048, K=512)
    {
        dim3 grid(SS / 128, SS / 128, BB);
        sgemm<true, false><<<grid, 256>>>(q, k, nullptr, p, SS, SS, DD,
                                          (long long)SS * DD,
                                          (long long)SS * DD,
                                          (long long)SS * SS);
    }

    // 5) softmax over last dim, in place
    softmax_rows<<<BB * SS, 256>>>(p);

    // 6) out = probs @ v per batch  (M=2048, N=512, K=2048)
    {
        dim3 grid(DD / 128, SS / 128, BB);
        sgemm<false, false><<<grid, 256>>>(p, v, nullptr, out, SS, DD, SS,
                                           (long long)SS * SS,
                                           (long long)SS * DD,
                                           (long long)SS * DD);
    }
}

// round 3
// speedup vs baseline: 1.1258x; 1.1258x over previous
#include <cuda_runtime.h>
#include <math_constants.h>

// Problem dims (fixed by the reference)
#define BB 8
#define SS 2048
#define DD 512

// Scratch (allocation-free rule: __device__ globals)
__device__ float g_q[(size_t)BB * SS * DD];
__device__ float g_k[(size_t)BB * SS * DD];
__device__ float g_v[(size_t)BB * SS * DD];
__device__ float g_p[(size_t)BB * SS * SS];   // scores / probs, 128 MiB

// ---------------------------------------------------------------------------
// Register-blocked SGEMM, v2: +4-float smem padding (16B-aligned rows ->
// LDS.128 in the microkernel), double-buffered smem with register-staged
// global prefetch.
//   C[M,N] = A[M,K] @ B(' if TRANS_B)   (+ bias[N] if HAS_BIAS)
// A row-major lda=K. B row-major: NN -> [K,N] ldb=N ; NT -> [N,K] ldb=K.
// Block tile 128x128, K-tile 16, 256 threads, 8x8 per-thread microtile.
// blockIdx.z = batch; per-batch element strides sA/sB/sC.
// All dims are multiples of the tile sizes -> no bounds checks.
// ---------------------------------------------------------------------------
template <bool TRANS_B, bool HAS_BIAS>
__global__ __launch_bounds__(256, 2)
void sgemm(const float* __restrict__ A, const float* __restrict__ Bm,
           const float* __restrict__ bias, float* __restrict__ C,
           int M, int N, int K,
           long long sA, long long sB, long long sC)
{
    constexpr int BM = 128, BN = 128, BK = 16, PAD = 4;
    A  += (long long)blockIdx.z * sA;
    Bm += (long long)blockIdx.z * sB;
    C  += (long long)blockIdx.z * sC;

    __shared__ float As[2][BK][BM + PAD];
    __shared__ float Bs[2][BK][BN + PAD];

    const int tid = threadIdx.x;
    const int tx = tid & 15;        // 0..15 -> col group (n)
    const int ty = tid >> 4;        // 0..15 -> row group (m)
    const int bm = blockIdx.y * BM;
    const int bn = blockIdx.x * BN;

    // Per-thread load slots: 2 float4 for A, 2 for B.
    //   A (and B when TRANS_B): idx = tid + i*256; row = idx>>2 (0..127),
    //   c4 = (idx&3)*4 (k within tile).
    //   B (NN): row = idx>>5 (0..15 = k), c4 = (idx&31)*4 (n within tile).
    float4 ra[2], rb[2];

    // ---- prologue: load tile kk=0 into registers ----
    #pragma unroll
    for (int i = 0; i < 2; i++) {
        int idx = tid + i * 256;
        ra[i] = *(const float4*)(A + (long long)(bm + (idx >> 2)) * K + ((idx & 3) * 4));
        if (TRANS_B)
            rb[i] = *(const float4*)(Bm + (long long)(bn + (idx >> 2)) * K + ((idx & 3) * 4));
        else
            rb[i] = *(const float4*)(Bm + (long long)(idx >> 5) * N + bn + ((idx & 31) * 4));
    }

    // ---- store prologue tile to buffer 0 ----
    #pragma unroll
    for (int i = 0; i < 2; i++) {
        int idx = tid + i * 256;
        {
            int row = idx >> 2, c4 = (idx & 3) * 4;
            As[0][c4 + 0][row] = ra[i].x;
            As[0][c4 + 1][row] = ra[i].y;
            As[0][c4 + 2][row] = ra[i].z;
            As[0][c4 + 3][row] = ra[i].w;
        }
        if (TRANS_B) {
            int row = idx >> 2, c4 = (idx & 3) * 4;
            Bs[0][c4 + 0][row] = rb[i].x;
            Bs[0][c4 + 1][row] = rb[i].y;
            Bs[0][c4 + 2][row] = rb[i].z;
            Bs[0][c4 + 3][row] = rb[i].w;
        } else {
            int row = idx >> 5, c4 = (idx & 31) * 4;
            Bs[0][row][c4 + 0] = rb[i].x;
            Bs[0][row][c4 + 1] = rb[i].y;
            Bs[0][row][c4 + 2] = rb[i].z;
            Bs[0][row][c4 + 3] = rb[i].w;
        }
    }
    __syncthreads();

    float acc[8][8];
    #pragma unroll
    for (int i = 0; i < 8; i++)
        #pragma unroll
        for (int j = 0; j < 8; j++) acc[i][j] = 0.f;

    int buf = 0;
    for (int kk = BK; kk <= K; kk += BK) {
        const bool has_next = (kk < K);

        // ---- prefetch next tile into registers (latency hidden by compute) --
        if (has_next) {
            #pragma unroll
            for (int i = 0; i < 2; i++) {
                int idx = tid + i * 256;
                ra[i] = *(const float4*)(A + (long long)(bm + (idx >> 2)) * K + kk + ((idx & 3) * 4));
                if (TRANS_B)
                    rb[i] = *(const float4*)(Bm + (long long)(bn + (idx >> 2)) * K + kk + ((idx & 3) * 4));
                else
                    rb[i] = *(const float4*)(Bm + (long long)(kk + (idx >> 5)) * N + bn + ((idx & 31) * 4));
            }
        }

        // ---- FMA microkernel on current buffer (LDS.128 reads) ----
        {
            const float* Asb = &As[buf][0][0];
            const float* Bsb = &Bs[buf][0][0];
            #pragma unroll
            for (int k = 0; k < BK; k++) {
                float4 a0 = *(const float4*)(Asb + k * (BM + PAD) + ty * 8);
                float4 a1 = *(const float4*)(Asb + k * (BM + PAD) + ty * 8 + 4);
                float4 b0 = *(const float4*)(Bsb + k * (BN + PAD) + tx * 8);
                float4 b1 = *(const float4*)(Bsb + k * (BN + PAD) + tx * 8 + 4);
                float a[8] = {a0.x, a0.y, a0.z, a0.w, a1.x, a1.y, a1.z, a1.w};
                float b[8] = {b0.x, b0.y, b0.z, b0.w, b1.x, b1.y, b1.z, b1.w};
                #pragma unroll
                for (int i = 0; i < 8; i++)
                    #pragma unroll
                    for (int j = 0; j < 8; j++)
                        acc[i][j] = fmaf(a[i], b[j], acc[i][j]);
            }
        }

        // ---- store prefetched tile into the other buffer ----
        if (has_next) {
            int nb = buf ^ 1;
            #pragma unroll
            for (int i = 0; i < 2; i++) {
                int idx = tid + i * 256;
                {
                    int row = idx >> 2, c4 = (idx & 3) * 4;
                    As[nb][c4 + 0][row] = ra[i].x;
                    As[nb][c4 + 1][row] = ra[i].y;
                    As[nb][c4 + 2][row] = ra[i].z;
                    As[nb][c4 + 3][row] = ra[i].w;
                }
                if (TRANS_B) {
                    int row = idx >> 2, c4 = (idx & 3) * 4;
                    Bs[nb][c4 + 0][row] = rb[i].x;
                    Bs[nb][c4 + 1][row] = rb[i].y;
                    Bs[nb][c4 + 2][row] = rb[i].z;
                    Bs[nb][c4 + 3][row] = rb[i].w;
                } else {
                    int row = idx >> 5, c4 = (idx & 31) * 4;
                    Bs[nb][row][c4 + 0] = rb[i].x;
                    Bs[nb][row][c4 + 1] = rb[i].y;
                    Bs[nb][row][c4 + 2] = rb[i].z;
                    Bs[nb][row][c4 + 3] = rb[i].w;
                }
            }
            __syncthreads();
            buf = nb;
        }
    }

    // ---- epilogue (+bias) ----
    #pragma unroll
    for (int i = 0; i < 8; i++) {
        long long crow = (long long)(bm + ty * 8 + i) * N + bn + tx * 8;
        #pragma unroll
        for (int j = 0; j < 8; j += 4) {
            float4 o;
            if (HAS_BIAS) {
                o.x = acc[i][j + 0] + bias[bn + tx * 8 + j + 0];
                o.y = acc[i][j + 1] + bias[bn + tx * 8 + j + 1];
                o.z = acc[i][j + 2] + bias[bn + tx * 8 + j + 2];
                o.w = acc[i][j + 3] + bias[bn + tx * 8 + j + 3];
            } else {
                o.x = acc[i][j + 0];
                o.y = acc[i][j + 1];
                o.z = acc[i][j + 2];
                o.w = acc[i][j + 3];
            }
            *(float4*)(C + crow + j) = o;
        }
    }
}

// ---------------------------------------------------------------------------
// Row softmax, in-place. One block per row of 2048 floats; 256 threads x 8.
// ---------------------------------------------------------------------------
__global__ __launch_bounds__(256)
void softmax_rows(float* __restrict__ p)
{
    __shared__ float red[32];
    const long long row = blockIdx.x;
    float* r = p + row * (long long)SS;
    const int tid = threadIdx.x;
    const int lane = tid & 31, wid = tid >> 5;

    float v[8];
    float m = -CUDART_INF_F;
    #pragma unroll
    for (int i = 0; i < 8; i++) {
        v[i] = r[tid + i * 256];
        m = fmaxf(m, v[i]);
    }
    // block max
    #pragma unroll
    for (int o = 16; o > 0; o >>= 1) m = fmaxf(m, __shfl_xor_sync(0xffffffffu, m, o));
    if (lane == 0) red[wid] = m;
    __syncthreads();
    if (wid == 0) {
        float t = (lane < 8) ? red[lane] : -CUDART_INF_F;
        #pragma unroll
        for (int o = 16; o > 0; o >>= 1) t = fmaxf(t, __shfl_xor_sync(0xffffffffu, t, o));
        red[lane] = t;
    }
    __syncthreads();
    m = red[0];

    float s = 0.f;
    #pragma unroll
    for (int i = 0; i < 8; i++) {
        v[i] = expf(v[i] - m);
        s += v[i];
    }
    #pragma unroll
    for (int o = 16; o > 0; o >>= 1) s += __shfl_xor_sync(0xffffffffu, s, o);
    __syncthreads();
    if (lane == 0) red[wid] = s;
    __syncthreads();
    if (wid == 0) {
        float t = (lane < 8) ? red[lane] : 0.f;
        #pragma unroll
        for (int o = 16; o > 0; o >>= 1) t += __shfl_xor_sync(0xffffffffu, t, o);
        red[lane] = t;
    }
    __syncthreads();
    const float inv = 1.0f / red[0];

    #pragma unroll
    for (int i = 0; i < 8; i++) r[tid + i * 256] = v[i] * inv;
}

// ---------------------------------------------------------------------------
extern "C" void kernel_launch(void* const* d_in, const int* in_sizes, int n_in,
                              void* d_out, int out_size)
{
    const float* x  = (const float*)d_in[0];
    const float* Wq = (const float*)d_in[1];
    const float* bq = (const float*)d_in[2];
    const float* Wk = (const float*)d_in[3];
    const float* bk = (const float*)d_in[4];
    const float* Wv = (const float*)d_in[5];
    const float* bv = (const float*)d_in[6];
    float* out = (float*)d_out;

    float *q, *k, *v, *p;
    cudaGetSymbolAddress((void**)&q, g_q);
    cudaGetSymbolAddress((void**)&k, g_k);
    cudaGetSymbolAddress((void**)&v, g_v);
    cudaGetSymbolAddress((void**)&p, g_p);

    const int M = BB * SS;       // 16384 rows for projections

    // 1-3) q/k/v = x @ W + b   (M=16384, N=512, K=512)
    {
        dim3 grid(DD / 128, M / 128, 1);
        sgemm<false, true><<<grid, 256>>>(x, Wq, bq, q, M, DD, DD, 0, 0, 0);
        sgemm<false, true><<<grid, 256>>>(x, Wk, bk, k, M, DD, DD, 0, 0, 0);
        sgemm<false, true><<<grid, 256>>>(x, Wv, bv, v, M, DD, DD, 0, 0, 0);
    }

    // 4) scores = q @ k^T per batch  (M=N=2048, K=512)
    {
        dim3 grid(SS / 128, SS / 128, BB);
        sgemm<true, false><<<grid, 256>>>(q, k, nullptr, p, SS, SS, DD,
                                          (long long)SS * DD,
                                          (long long)SS * DD,
                                          (long long)SS * SS);
    }

    // 5) softmax over last dim, in place
    softmax_rows<<<BB * SS, 256>>>(p);

    // 6) out = probs @ v per batch  (M=2048, N=512, K=2048)
    {
        dim3 grid(DD / 128, SS / 128, BB);
        sgemm<false, false><<<grid, 256>>>(p, v, nullptr, out, SS, DD, SS,
                                           (long long)SS * SS,
                                           (long long)SS * DD,
                                           (long long)SS * DD);
    }
}

// round 5
// speedup vs baseline: 1.2304x; 1.0929x over previous
#include <cuda_runtime.h>
#include <math_constants.h>

// Problem dims (fixed by the reference)
#define BB 8
#define SS 2048
#define DD 512

// Scratch (allocation-free rule: __device__ globals)
__device__ float g_q[(size_t)BB * SS * DD];
__device__ float g_k[(size_t)BB * SS * DD];
__device__ float g_v[(size_t)BB * SS * DD];
__device__ float g_p[(size_t)BB * SS * SS];   // scores / probs, 128 MiB

// ---- packed fp32 helpers (Blackwell f32x2 pipe; ptxas won't auto-fuse) ----
__device__ __forceinline__ unsigned long long pack2_dup(float x) {
    unsigned long long r;
    asm("mov.b64 %0, {%1, %1};" : "=l"(r) : "r"(__float_as_uint(x)));
    return r;
}
__device__ __forceinline__ void fma2(unsigned long long& d,
                                     unsigned long long a,
                                     unsigned long long b) {
    asm("fma.rn.f32x2 %0, %1, %2, %0;" : "+l"(d) : "l"(a), "l"(b));
}
__device__ __forceinline__ float2 unpack2(unsigned long long v) {
    float2 r;
    asm("mov.b64 {%0, %1}, %2;" : "=f"(r.x), "=f"(r.y) : "l"(v));
    return r;
}

// ---------------------------------------------------------------------------
// Register-blocked SGEMM, v3: f32x2 packed-FMA microkernel.
//   C[M,N] = A[M,K] @ B(' if TRANS_B)   (+ bias[N] if HAS_BIAS)
// Block tile 128x128, K-tile 16, 256 threads, 8x8 per-thread microtile held
// as 8x4 f32x2 accumulators. Double-buffered smem, register-staged prefetch.
// ---------------------------------------------------------------------------
template <bool TRANS_B, bool HAS_BIAS>
__global__ __launch_bounds__(256, 2)
void sgemm(const float* __restrict__ A, const float* __restrict__ Bm,
           const float* __restrict__ bias, float* __restrict__ C,
           int M, int N, int K,
           long long sA, long long sB, long long sC)
{
    constexpr int BM = 128, BN = 128, BK = 16, PAD = 4;
    A  += (long long)blockIdx.z * sA;
    Bm += (long long)blockIdx.z * sB;
    C  += (long long)blockIdx.z * sC;

    __shared__ float As[2][BK][BM + PAD];
    __shared__ float Bs[2][BK][BN + PAD];

    const int tid = threadIdx.x;
    const int tx = tid & 15;        // 0..15 -> col group (n)
    const int ty = tid >> 4;        // 0..15 -> row group (m)
    const int bm = blockIdx.y * BM;
    const int bn = blockIdx.x * BN;

    float4 ra[2], rb[2];

    // ---- prologue: load tile kk=0 into registers ----
    #pragma unroll
    for (int i = 0; i < 2; i++) {
        int idx = tid + i * 256;
        ra[i] = *(const float4*)(A + (long long)(bm + (idx >> 2)) * K + ((idx & 3) * 4));
        if (TRANS_B)
            rb[i] = *(const float4*)(Bm + (long long)(bn + (idx >> 2)) * K + ((idx & 3) * 4));
        else
            rb[i] = *(const float4*)(Bm + (long long)(idx >> 5) * N + bn + ((idx & 31) * 4));
    }

    // ---- store prologue tile to buffer 0 ----
    #pragma unroll
    for (int i = 0; i < 2; i++) {
        int idx = tid + i * 256;
        {
            int row = idx >> 2, c4 = (idx & 3) * 4;
            As[0][c4 + 0][row] = ra[i].x;
            As[0][c4 + 1][row] = ra[i].y;
            As[0][c4 + 2][row] = ra[i].z;
            As[0][c4 + 3][row] = ra[i].w;
        }
        if (TRANS_B) {
            int row = idx >> 2, c4 = (idx & 3) * 4;
            Bs[0][c4 + 0][row] = rb[i].x;
            Bs[0][c4 + 1][row] = rb[i].y;
            Bs[0][c4 + 2][row] = rb[i].z;
            Bs[0][c4 + 3][row] = rb[i].w;
        } else {
            int row = idx >> 5, c4 = (idx & 31) * 4;
            Bs[0][row][c4 + 0] = rb[i].x;
            Bs[0][row][c4 + 1] = rb[i].y;
            Bs[0][row][c4 + 2] = rb[i].z;
            Bs[0][row][c4 + 3] = rb[i].w;
        }
    }
    __syncthreads();

    // 8x8 microtile as 8 rows x 4 f32x2 column-pairs
    unsigned long long acc[8][4];
    #pragma unroll
    for (int i = 0; i < 8; i++)
        #pragma unroll
        for (int j = 0; j < 4; j++) acc[i][j] = 0ull;   // (0.f, 0.f)

    int buf = 0;
    for (int kk = BK; kk <= K; kk += BK) {
        const bool has_next = (kk < K);

        // ---- prefetch next tile into registers ----
        if (has_next) {
            #pragma unroll
            for (int i = 0; i < 2; i++) {
                int idx = tid + i * 256;
                ra[i] = *(const float4*)(A + (long long)(bm + (idx >> 2)) * K + kk + ((idx & 3) * 4));
                if (TRANS_B)
                    rb[i] = *(const float4*)(Bm + (long long)(bn + (idx >> 2)) * K + kk + ((idx & 3) * 4));
                else
                    rb[i] = *(const float4*)(Bm + (long long)(kk + (idx >> 5)) * N + bn + ((idx & 31) * 4));
            }
        }

        // ---- f32x2 FMA microkernel on current buffer ----
        {
            const float* Asb = &As[buf][0][0];
            const float* Bsb = &Bs[buf][0][0];
            #pragma unroll
            for (int k = 0; k < BK; k++) {
                float4 a0 = *(const float4*)(Asb + k * (BM + PAD) + ty * 8);
                float4 a1 = *(const float4*)(Asb + k * (BM + PAD) + ty * 8 + 4);
                // b pairs straight from smem as 64-bit lanes (consecutive floats)
                ulonglong2 bq0 = *(const ulonglong2*)(Bsb + k * (BN + PAD) + tx * 8);
                ulonglong2 bq1 = *(const ulonglong2*)(Bsb + k * (BN + PAD) + tx * 8 + 4);
                unsigned long long bp[4] = {bq0.x, bq0.y, bq1.x, bq1.y};
                float a[8] = {a0.x, a0.y, a0.z, a0.w, a1.x, a1.y, a1.z, a1.w};
                #pragma unroll
                for (int i = 0; i < 8; i++) {
                    unsigned long long ap = pack2_dup(a[i]);
                    #pragma unroll
                    for (int j = 0; j < 4; j++) fma2(acc[i][j], ap, bp[j]);
                }
            }
        }

        // ---- store prefetched tile into the other buffer ----
        if (has_next) {
            int nb = buf ^ 1;
            #pragma unroll
            for (int i = 0; i < 2; i++) {
                int idx = tid + i * 256;
                {
                    int row = idx >> 2, c4 = (idx & 3) * 4;
                    As[nb][c4 + 0][row] = ra[i].x;
                    As[nb][c4 + 1][row] = ra[i].y;
                    As[nb][c4 + 2][row] = ra[i].z;
                    As[nb][c4 + 3][row] = ra[i].w;
                }
                if (TRANS_B) {
                    int row = idx >> 2, c4 = (idx & 3) * 4;
                    Bs[nb][c4 + 0][row] = rb[i].x;
                    Bs[nb][c4 + 1][row] = rb[i].y;
                    Bs[nb][c4 + 2][row] = rb[i].z;
                    Bs[nb][c4 + 3][row] = rb[i].w;
                } else {
                    int row = idx >> 5, c4 = (idx & 31) * 4;
                    Bs[nb][row][c4 + 0] = rb[i].x;
                    Bs[nb][row][c4 + 1] = rb[i].y;
                    Bs[nb][row][c4 + 2] = rb[i].z;
                    Bs[nb][row][c4 + 3] = rb[i].w;
                }
            }
            __syncthreads();
            buf = nb;
        }
    }

    // ---- epilogue (+bias) ----
    #pragma unroll
    for (int i = 0; i < 8; i++) {
        long long crow = (long long)(bm + ty * 8 + i) * N + bn + tx * 8;
        #pragma unroll
        for (int jp = 0; jp < 2; jp++) {           // two float4 stores
            float2 p0 = unpack2(acc[i][jp * 2 + 0]);
            float2 p1 = unpack2(acc[i][jp * 2 + 1]);
            float4 o;
            if (HAS_BIAS) {
                const float* bb = bias + bn + tx * 8 + jp * 4;
                o.x = p0.x + bb[0];
                o.y = p0.y + bb[1];
                o.z = p1.x + bb[2];
                o.w = p1.y + bb[3];
            } else {
                o.x = p0.x; o.y = p0.y; o.z = p1.x; o.w = p1.y;
            }
            *(float4*)(C + crow + jp * 4) = o;
        }
    }
}

// ---------------------------------------------------------------------------
// Row softmax, in-place. One block per row of 2048 floats; 256 threads x 8.
// ---------------------------------------------------------------------------
__global__ __launch_bounds__(256)
void softmax_rows(float* __restrict__ p)
{
    __shared__ float red[32];
    const long long row = blockIdx.x;
    float* r = p + row * (long long)SS;
    const int tid = threadIdx.x;
    const int lane = tid & 31, wid = tid >> 5;

    float v[8];
    float m = -CUDART_INF_F;
    #pragma unroll
    for (int i = 0; i < 8; i++) {
        v[i] = r[tid + i * 256];
        m = fmaxf(m, v[i]);
    }
    #pragma unroll
    for (int o = 16; o > 0; o >>= 1) m = fmaxf(m, __shfl_xor_sync(0xffffffffu, m, o));
    if (lane == 0) red[wid] = m;
    __syncthreads();
    if (wid == 0) {
        float t = (lane < 8) ? red[lane] : -CUDART_INF_F;
        #pragma unroll
        for (int o = 16; o > 0; o >>= 1) t = fmaxf(t, __shfl_xor_sync(0xffffffffu, t, o));
        red[lane] = t;
    }
    __syncthreads();
    m = red[0];

    float s = 0.f;
    #pragma unroll
    for (int i = 0; i < 8; i++) {
        v[i] = expf(v[i] - m);
        s += v[i];
    }
    #pragma unroll
    for (int o = 16; o > 0; o >>= 1) s += __shfl_xor_sync(0xffffffffu, s, o);
    __syncthreads();
    if (lane == 0) red[wid] = s;
    __syncthreads();
    if (wid == 0) {
        float t = (lane < 8) ? red[lane] : 0.f;
        #pragma unroll
        for (int o = 16; o > 0; o >>= 1) t += __shfl_xor_sync(0xffffffffu, t, o);
        red[lane] = t;
    }
    __syncthreads();
    const float inv = 1.0f / red[0];

    #pragma unroll
    for (int i = 0; i < 8; i++) r[tid + i * 256] = v[i] * inv;
}

// ---------------------------------------------------------------------------
extern "C" void kernel_launch(void* const* d_in, const int* in_sizes, int n_in,
                              void* d_out, int out_size)
{
    const float* x  = (const float*)d_in[0];
    const float* Wq = (const float*)d_in[1];
    const float* bq = (const float*)d_in[2];
    const float* Wk = (const float*)d_in[3];
    const float* bk = (const float*)d_in[4];
    const float* Wv = (const float*)d_in[5];
    const float* bv = (const float*)d_in[6];
    float* out = (float*)d_out;

    float *q, *k, *v, *p;
    cudaGetSymbolAddress((void**)&q, g_q);
    cudaGetSymbolAddress((void**)&k, g_k);
    cudaGetSymbolAddress((void**)&v, g_v);
    cudaGetSymbolAddress((void**)&p, g_p);

    const int M = BB * SS;       // 16384 rows for projections

    // 1-3) q/k/v = x @ W + b   (M=16384, N=512, K=512)
    {
        dim3 grid(DD / 128, M / 128, 1);
        sgemm<false, true><<<grid, 256>>>(x, Wq, bq, q, M, DD, DD, 0, 0, 0);
        sgemm<false, true><<<grid, 256>>>(x, Wk, bk, k, M, DD, DD, 0, 0, 0);
        sgemm<false, true><<<grid, 256>>>(x, Wv, bv, v, M, DD, DD, 0, 0, 0);
    }

    // 4) scores = q @ k^T per batch  (M=N=2048, K=512)
    {
        dim3 grid(SS / 128, SS / 128, BB);
        sgemm<true, false><<<grid, 256>>>(q, k, nullptr, p, SS, SS, DD,
                                          (long long)SS * DD,
                                          (long long)SS * DD,
                                          (long long)SS * SS);
    }

    // 5) softmax over last dim, in place
    softmax_rows<<<BB * SS, 256>>>(p);

    // 6) out = probs @ v per batch  (M=2048, N=512, K=2048)
    {
        dim3 grid(DD / 128, SS / 128, BB);
        sgemm<false, false><<<grid, 256>>>(p, v, nullptr, out, SS, DD, SS,
                                           (long long)SS * SS,
                                           (long long)SS * DD,
                                           (long long)SS * DD);
    }
}

// round 9
// speedup vs baseline: 2.0400x; 1.6580x over previous
#include <cuda_runtime.h>
#include <cuda_bf16.h>
#include <cstdint>
#include <math_constants.h>

// Problem dims (fixed by the reference)
#define BB 8
#define SS 2048
#define DD 512
#define MTOT (BB*SS)

// ---------------- scratch (__device__ globals; no allocations) -------------
__device__ __nv_bfloat16 g_xhi[(size_t)MTOT * DD];
__device__ __nv_bfloat16 g_xlo[(size_t)MTOT * DD];
__device__ __nv_bfloat16 g_wth[3][(size_t)DD * DD];   // W^T hi (q,k,v)
__device__ __nv_bfloat16 g_wtl[3][(size_t)DD * DD];   // W^T lo
__device__ __nv_bfloat16 g_qhi[(size_t)MTOT * DD], g_qlo[(size_t)MTOT * DD];
__device__ __nv_bfloat16 g_khi[(size_t)MTOT * DD], g_klo[(size_t)MTOT * DD];
__device__ __nv_bfloat16 g_vhi[(size_t)MTOT * DD], g_vlo[(size_t)MTOT * DD];
__device__ __nv_bfloat16 g_vthi[(size_t)BB * DD * SS], g_vtlo[(size_t)BB * DD * SS];
__device__ float        g_scores[(size_t)BB * SS * SS];          // 128 MiB
__device__ __nv_bfloat16 g_phi[(size_t)BB * SS * SS], g_plo[(size_t)BB * SS * SS];

// ---------------- helpers --------------------------------------------------
__device__ __forceinline__ uint32_t smem_u32(const void* p) {
    uint32_t a;
    asm("{ .reg .u64 t; cvta.to.shared.u64 t, %1; cvt.u32.u64 %0, t; }"
        : "=r"(a) : "l"(p));
    return a;
}

__device__ __forceinline__ void cp_async16(uint32_t saddr, const void* gaddr) {
    asm volatile("cp.async.cg.shared.global [%0], [%1], 16;"
                 :: "r"(saddr), "l"(gaddr));
}

__device__ __forceinline__ void ldmat4(uint32_t& r0, uint32_t& r1,
                                       uint32_t& r2, uint32_t& r3, uint32_t addr) {
    asm volatile("ldmatrix.sync.aligned.m8n8.x4.shared.b16 {%0,%1,%2,%3}, [%4];"
                 : "=r"(r0), "=r"(r1), "=r"(r2), "=r"(r3) : "r"(addr));
}

__device__ __forceinline__ void mma16816(float* c, const uint32_t* a,
                                         uint32_t b0, uint32_t b1) {
    asm volatile(
        "mma.sync.aligned.m16n8k16.row.col.f32.bf16.bf16.f32 "
        "{%0,%1,%2,%3}, {%4,%5,%6,%7}, {%8,%9}, {%0,%1,%2,%3};"
        : "+f"(c[0]), "+f"(c[1]), "+f"(c[2]), "+f"(c[3])
        : "r"(a[0]), "r"(a[1]), "r"(a[2]), "r"(a[3]), "r"(b0), "r"(b1));
}

// ---------------- warp-MMA bf16 GEMM (legacy HMMA path, plain PTX) ----------
// C[M,N] = A' @ B'^T, A' = [Ahi|Alo|Ahi], B' = [Bhi|Bhi|Blo] along K (3-term
// float-split; lo*lo dropped, rel err ~2^-18). A row-major [M,K], B row-major
// [N,K]. BM=BN=128, BK=32, 256 threads = 8 warps (2x4), warp tile 64x32.
// cp.async.cg double-buffered smem, rows padded to 40 bf16 (80B stride =>
// conflict-free ldmatrix). fp32 accumulators in registers.
// EPI 0: f32 store. EPI 1: +bias, hi/lo bf16 split store.
static constexpr int GBM = 128, GBN = 128, GBK = 32;
static constexpr int SMROW = 40;                       // padded row, bf16
static constexpr int SMBUF = GBM * SMROW * 2;          // 10240 B per tile buf

template <int EPI>
__global__ __launch_bounds__(256, 2)
void mma_gemm(const __nv_bfloat16* __restrict__ Ahi, const __nv_bfloat16* __restrict__ Alo,
              const __nv_bfloat16* __restrict__ Bhi, const __nv_bfloat16* __restrict__ Blo,
              const float* __restrict__ bias,
              float* __restrict__ Cf,
              __nv_bfloat16* __restrict__ Chi, __nv_bfloat16* __restrict__ Clo,
              int K, int lda, int ldb, int ldc,
              long long sA, long long sB, long long sC)
{
    __shared__ __nv_bfloat16 As[2][GBM][SMROW];
    __shared__ __nv_bfloat16 Bs[2][GBN][SMROW];

    const int tid = threadIdx.x;
    const int lane = tid & 31, wid = tid >> 5;
    const int wm = wid & 1, wn = wid >> 1;            // 2 x 4 warp grid
    const int bm = blockIdx.y * GBM;
    const int bn = blockIdx.x * GBN;
    Ahi += (long long)blockIdx.z * sA;  Alo += (long long)blockIdx.z * sA;
    Bhi += (long long)blockIdx.z * sB;  Blo += (long long)blockIdx.z * sB;

    const uint32_t aBase = smem_u32(As);
    const uint32_t bBase = smem_u32(Bs);

    const int Ksub = K >> 5;            // 32-elem chunks per segment
    const int NC = 3 * Ksub;

    // issue async loads for chunk c into buffer c&1
    auto issue = [&](int c) {
        const int seg = c / Ksub;
        const int kc = (c - seg * Ksub) << 5;
        const __nv_bfloat16* Ap = ((seg == 1) ? Alo : Ahi) + (long long)bm * lda + kc;
        const __nv_bfloat16* Bp = ((seg == 2) ? Blo : Bhi) + (long long)bn * ldb + kc;
        const uint32_t ad = aBase + (c & 1) * SMBUF;
        const uint32_t bd = bBase + (c & 1) * SMBUF;
        #pragma unroll
        for (int i = 0; i < 2; i++) {
            int idx = tid + i * 256;           // 512 16B chunks per tile
            int row = idx >> 2, ch = idx & 3;  // ch: 8-elem (16B) column group
            cp_async16(ad + row * 80 + ch * 16, Ap + (long long)row * lda + ch * 8);
            cp_async16(bd + row * 80 + ch * 16, Bp + (long long)row * ldb + ch * 8);
        }
        asm volatile("cp.async.commit_group;");
    };

    float acc[4][4][4];
    #pragma unroll
    for (int i = 0; i < 4; i++)
        #pragma unroll
        for (int j = 0; j < 4; j++)
            #pragma unroll
            for (int r = 0; r < 4; r++) acc[i][j][r] = 0.f;

    issue(0);

    const int m0 = wm * 64, n0 = wn * 32;
    const int lrow = lane & 15, lhalf = lane >> 4;

    for (int c = 0; c < NC; c++) {
        if (c + 1 < NC) {
            issue(c + 1);
            asm volatile("cp.async.wait_group 1;");
        } else {
            asm volatile("cp.async.wait_group 0;");
        }
        __syncthreads();

        const uint32_t ab = aBase + (c & 1) * SMBUF;
        const uint32_t bb = bBase + (c & 1) * SMBUF;

        #pragma unroll
        for (int ks = 0; ks < 2; ks++) {
            uint32_t afr[4][4];
            uint32_t bfr[4][2];
            #pragma unroll
            for (int mt = 0; mt < 4; mt++) {
                uint32_t addr = ab + ((m0 + mt * 16 + lrow) * SMROW + ks * 16 + lhalf * 8) * 2;
                ldmat4(afr[mt][0], afr[mt][1], afr[mt][2], afr[mt][3], addr);
            }
            #pragma unroll
            for (int bt = 0; bt < 2; bt++) {
                uint32_t r0, r1, r2, r3;
                uint32_t addr = bb + ((n0 + bt * 16 + lrow) * SMROW + ks * 16 + lhalf * 8) * 2;
                ldmat4(r0, r1, r2, r3, addr);
                bfr[2 * bt + 0][0] = r0;  bfr[2 * bt + 1][0] = r1;
                bfr[2 * bt + 0][1] = r2;  bfr[2 * bt + 1][1] = r3;
            }
            #pragma unroll
            for (int mt = 0; mt < 4; mt++)
                #pragma unroll
                for (int nt = 0; nt < 4; nt++)
                    mma16816(acc[mt][nt], afr[mt], bfr[nt][0], bfr[nt][1]);
        }
        __syncthreads();
    }

    // ---- epilogue ----
    const int r0 = lane >> 2, cql = (lane & 3) * 2;
    #pragma unroll
    for (int mt = 0; mt < 4; mt++) {
        #pragma unroll
        for (int nt = 0; nt < 4; nt++) {
            const int row = bm + m0 + mt * 16 + r0;
            const int col = bn + n0 + nt * 8 + cql;
            if (EPI == 0) {
                float* d0 = Cf + (long long)blockIdx.z * sC + (long long)row * ldc + col;
                float* d1 = d0 + 8LL * ldc;
                *(float2*)d0 = make_float2(acc[mt][nt][0], acc[mt][nt][1]);
                *(float2*)d1 = make_float2(acc[mt][nt][2], acc[mt][nt][3]);
            } else {
                const float b0 = bias[col], b1 = bias[col + 1];
                #pragma unroll
                for (int h = 0; h < 2; h++) {
                    const long long base = (long long)(row + 8 * h) * ldc + col;
                    float y0 = acc[mt][nt][2 * h + 0] + b0;
                    float y1 = acc[mt][nt][2 * h + 1] + b1;
                    __nv_bfloat16 h0 = __float2bfloat16_rn(y0);
                    __nv_bfloat16 h1 = __float2bfloat16_rn(y1);
                    __nv_bfloat162 hv; hv.x = h0; hv.y = h1;
                    __nv_bfloat162 lv;
                    lv.x = __float2bfloat16_rn(y0 - __bfloat162float(h0));
                    lv.y = __float2bfloat16_rn(y1 - __bfloat162float(h1));
                    *(__nv_bfloat162*)(Chi + base) = hv;
                    *(__nv_bfloat162*)(Clo + base) = lv;
                }
            }
        }
    }
}

// ---------------- aux kernels ----------------------------------------------
__global__ void split_f32(const float* __restrict__ in,
                          __nv_bfloat16* __restrict__ hi, __nv_bfloat16* __restrict__ lo,
                          int n)
{
    int i = blockIdx.x * blockDim.x + threadIdx.x;
    if (i < n) {
        float x = in[i];
        __nv_bfloat16 h = __float2bfloat16_rn(x);
        hi[i] = h;
        lo[i] = __float2bfloat16_rn(x - __bfloat162float(h));
    }
}

// W [K=512, N=512] f32 -> W^T hi/lo bf16 [N, K]
__global__ void splitT_w(const float* __restrict__ W,
                         __nv_bfloat16* __restrict__ th, __nv_bfloat16* __restrict__ tl)
{
    __shared__ float s[32][33];
    int e0 = blockIdx.x * 32, k0 = blockIdx.y * 32;
    int tx = threadIdx.x, ty = threadIdx.y;       // (32, 8)
    #pragma unroll
    for (int i = 0; i < 4; i++)
        s[ty + 8 * i][tx] = W[(k0 + ty + 8 * i) * DD + e0 + tx];
    __syncthreads();
    #pragma unroll
    for (int i = 0; i < 4; i++) {
        float v = s[tx][ty + 8 * i];              // = W[k0+tx][e0+ty+8i]
        __nv_bfloat16 h = __float2bfloat16_rn(v);
        long long dst = (long long)(e0 + ty + 8 * i) * DD + k0 + tx;
        th[dst] = h;
        tl[dst] = __float2bfloat16_rn(v - __bfloat162float(h));
    }
}

// v hi/lo [B*S, D] -> v^T hi/lo [B, D, S]
__global__ void transpose_split(const __nv_bfloat16* __restrict__ ih,
                                const __nv_bfloat16* __restrict__ il,
                                __nv_bfloat16* __restrict__ oh,
                                __nv_bfloat16* __restrict__ ol)
{
    __shared__ __nv_bfloat16 th[32][33], tl[32][33];
    int s0 = blockIdx.x * 32, e0 = blockIdx.y * 32, b = blockIdx.z;
    int tx = threadIdx.x, ty = threadIdx.y;       // (32, 8)
    #pragma unroll
    for (int i = 0; i < 4; i++) {
        long long src = ((long long)b * SS + s0 + ty + 8 * i) * DD + e0 + tx;
        th[ty + 8 * i][tx] = ih[src];
        tl[ty + 8 * i][tx] = il[src];
    }
    __syncthreads();
    #pragma unroll
    for (int i = 0; i < 4; i++) {
        long long dst = ((long long)b * DD + e0 + ty + 8 * i) * SS + s0 + tx;
        oh[dst] = th[tx][ty + 8 * i];
        ol[dst] = tl[tx][ty + 8 * i];
    }
}

// softmax over rows of 2048 f32 scores -> P split into hi/lo bf16
__global__ __launch_bounds__(256)
void softmax_split(const float* __restrict__ sc,
                   __nv_bfloat16* __restrict__ ph, __nv_bfloat16* __restrict__ pl)
{
    __shared__ float red[32];
    const long long row = blockIdx.x;
    const float* r = sc + row * (long long)SS;
    const int tid = threadIdx.x;
    const int lane = tid & 31, wid = tid >> 5;

    float v[8];
    float m = -CUDART_INF_F;
    #pragma unroll
    for (int i = 0; i < 8; i++) { v[i] = r[tid + i * 256]; m = fmaxf(m, v[i]); }
    #pragma unroll
    for (int o = 16; o > 0; o >>= 1) m = fmaxf(m, __shfl_xor_sync(0xffffffffu, m, o));
    if (lane == 0) red[wid] = m;
    __syncthreads();
    if (wid == 0) {
        float t = (lane < 8) ? red[lane] : -CUDART_INF_F;
        #pragma unroll
        for (int o = 16; o > 0; o >>= 1) t = fmaxf(t, __shfl_xor_sync(0xffffffffu, t, o));
        red[lane] = t;
    }
    __syncthreads();
    m = red[0];

    float s = 0.f;
    #pragma unroll
    for (int i = 0; i < 8; i++) { v[i] = expf(v[i] - m); s += v[i]; }
    #pragma unroll
    for (int o = 16; o > 0; o >>= 1) s += __shfl_xor_sync(0xffffffffu, s, o);
    __syncthreads();
    if (lane == 0) red[wid] = s;
    __syncthreads();
    if (wid == 0) {
        float t = (lane < 8) ? red[lane] : 0.f;
        #pragma unroll
        for (int o = 16; o > 0; o >>= 1) t += __shfl_xor_sync(0xffffffffu, t, o);
        red[lane] = t;
    }
    __syncthreads();
    const float inv = 1.0f / red[0];

    #pragma unroll
    for (int i = 0; i < 8; i++) {
        float p = v[i] * inv;
        __nv_bfloat16 h = __float2bfloat16_rn(p);
        long long idx = row * (long long)SS + tid + i * 256;
        ph[idx] = h;
        pl[idx] = __float2bfloat16_rn(p - __bfloat162float(h));
    }
}

// ---------------------------------------------------------------------------
extern "C" void kernel_launch(void* const* d_in, const int* in_sizes, int n_in,
                              void* d_out, int out_size)
{
    const float* x  = (const float*)d_in[0];
    const float* Wq = (const float*)d_in[1];
    const float* bq = (const float*)d_in[2];
    const float* Wk = (const float*)d_in[3];
    const float* bk = (const float*)d_in[4];
    const float* Wv = (const float*)d_in[5];
    const float* bv = (const float*)d_in[6];
    float* out = (float*)d_out;

    __nv_bfloat16 *xhi, *xlo, *wth, *wtl, *qhi, *qlo, *khi, *klo, *vhi, *vlo,
                  *vthi, *vtlo, *phi, *plo;
    float* scores;
    cudaGetSymbolAddress((void**)&xhi, g_xhi);
    cudaGetSymbolAddress((void**)&xlo, g_xlo);
    cudaGetSymbolAddress((void**)&wth, g_wth);
    cudaGetSymbolAddress((void**)&wtl, g_wtl);
    cudaGetSymbolAddress((void**)&qhi, g_qhi);
    cudaGetSymbolAddress((void**)&qlo, g_qlo);
    cudaGetSymbolAddress((void**)&khi, g_khi);
    cudaGetSymbolAddress((void**)&klo, g_klo);
    cudaGetSymbolAddress((void**)&vhi, g_vhi);
    cudaGetSymbolAddress((void**)&vlo, g_vlo);
    cudaGetSymbolAddress((void**)&vthi, g_vthi);
    cudaGetSymbolAddress((void**)&vtlo, g_vtlo);
    cudaGetSymbolAddress((void**)&scores, g_scores);
    cudaGetSymbolAddress((void**)&phi, g_phi);
    cudaGetSymbolAddress((void**)&plo, g_plo);

    const size_t WSZ = (size_t)DD * DD;

    // 1) splits
    split_f32<<<(MTOT * DD + 255) / 256, 256>>>(x, xhi, xlo, MTOT * DD);
    dim3 tb(32, 8);
    splitT_w<<<dim3(16, 16), tb>>>(Wq, wth + 0 * WSZ, wtl + 0 * WSZ);
    splitT_w<<<dim3(16, 16), tb>>>(Wk, wth + 1 * WSZ, wtl + 1 * WSZ);
    splitT_w<<<dim3(16, 16), tb>>>(Wv, wth + 2 * WSZ, wtl + 2 * WSZ);

    // 2) projections: q/k/v (+bias), outputs split bf16
    dim3 gp(DD / GBN, MTOT / GBM, 1);   // (4, 128, 1)
    mma_gemm<1><<<gp, 256>>>(xhi, xlo, wth + 0 * WSZ, wtl + 0 * WSZ, bq,
                             nullptr, qhi, qlo, DD, DD, DD, DD, 0, 0, 0);
    mma_gemm<1><<<gp, 256>>>(xhi, xlo, wth + 1 * WSZ, wtl + 1 * WSZ, bk,
                             nullptr, khi, klo, DD, DD, DD, DD, 0, 0, 0);
    mma_gemm<1><<<gp, 256>>>(xhi, xlo, wth + 2 * WSZ, wtl + 2 * WSZ, bv,
                             nullptr, vhi, vlo, DD, DD, DD, DD, 0, 0, 0);

    // 3) V^T splits for PV
    transpose_split<<<dim3(SS / 32, DD / 32, BB), tb>>>(vhi, vlo, vthi, vtlo);

    // 4) scores = q @ k^T per batch -> f32
    dim3 gqk(SS / GBN, SS / GBM, BB);   // (16, 16, 8)
    mma_gemm<0><<<gqk, 256>>>(qhi, qlo, khi, klo, nullptr,
                              scores, nullptr, nullptr,
                              DD, DD, DD, SS,
                              (long long)SS * DD, (long long)SS * DD,
                              (long long)SS * SS);

    // 5) softmax -> P hi/lo bf16
    softmax_split<<<BB * SS, 256>>>(scores, phi, plo);

    // 6) out = P @ V per batch -> f32
    dim3 gpv(DD / GBN, SS / GBM, BB);   // (4, 16, 8)
    mma_gemm<0><<<gpv, 256>>>(phi, plo, vthi, vtlo, nullptr,
                              out, nullptr, nullptr,
                              SS, SS, SS, DD,
                              (long long)SS * SS, (long long)DD * SS,
                              (long long)SS * DD);
}